// round 16
// baseline (speedup 1.0000x reference)
#include <cuda_runtime.h>
#include <cuda_bf16.h>
#include <stdint.h>
#include <cstdint>
#include <math.h>

#define MTOT 4096      // B*T
#define TLEN 2048
#define HQ   8
#define DKh  256
#define DVh  512
#define HID  2048
#define NQK  2048      // H*DK
#define NVG  4096      // H*DV

__device__ __align__(1024) unsigned char g_pool[637534208];

__device__ __forceinline__ uint32_t smem_to_u32(const void* p) {
    uint32_t a;
    asm("{ .reg .u64 t; cvta.to.shared.u64 t, %1; cvt.u32.u64 %0, t; }"
        : "=r"(a) : "l"(p));
    return a;
}
#define SMEM_SWIZZLE_128B(byte_offset) \
    ((byte_offset) ^ (((byte_offset) >> 3) & 0x70))
#define ROWSWZ(row, c2) ((c2) ^ (((row) & 7) << 4))
#define SWZ64(r, c16) ((c16) ^ ((((r) >> 1) & 3) << 4))

#define CP_ASYNC16(dst_u32, gptr) \
    asm volatile("cp.async.cg.shared.global [%0], [%1], 16;" \
                 :: "r"(dst_u32), "l"(gptr))
#define CP_COMMIT() asm volatile("cp.async.commit_group;" ::: "memory")
#define CP_WAIT(n)  asm volatile("cp.async.wait_group %0;" :: "n"(n) : "memory")

// -------- mma.sync / ldmatrix helpers --------
__device__ __forceinline__ void ldmx4(uint32_t& r0, uint32_t& r1, uint32_t& r2,
                                      uint32_t& r3, uint32_t addr) {
    asm volatile("ldmatrix.sync.aligned.m8n8.x4.shared.b16 {%0,%1,%2,%3}, [%4];"
                 : "=r"(r0), "=r"(r1), "=r"(r2), "=r"(r3) : "r"(addr));
}
__device__ __forceinline__ void ldmx4t(uint32_t& r0, uint32_t& r1, uint32_t& r2,
                                       uint32_t& r3, uint32_t addr) {
    asm volatile("ldmatrix.sync.aligned.m8n8.x4.trans.shared.b16 {%0,%1,%2,%3}, [%4];"
                 : "=r"(r0), "=r"(r1), "=r"(r2), "=r"(r3) : "r"(addr));
}
__device__ __forceinline__ void mma16816(float& c0, float& c1, float& c2, float& c3,
                                         uint32_t a0, uint32_t a1, uint32_t a2,
                                         uint32_t a3, uint32_t b0, uint32_t b1) {
    asm volatile(
        "mma.sync.aligned.m16n8k16.row.col.f32.bf16.bf16.f32 "
        "{%0,%1,%2,%3}, {%4,%5,%6,%7}, {%8,%9}, {%0,%1,%2,%3};"
        : "+f"(c0), "+f"(c1), "+f"(c2), "+f"(c3)
        : "r"(a0), "r"(a1), "r"(a2), "r"(a3), "r"(b0), "r"(b1));
}
__device__ __forceinline__ uint32_t pack_hi(float a, float b) {
    __nv_bfloat16 x = __float2bfloat16(a), y = __float2bfloat16(b);
    return ((uint32_t)*(uint16_t*)&y << 16) | *(uint16_t*)&x;
}
__device__ __forceinline__ uint32_t pack_lo(float a, float b) {
    __nv_bfloat16 x = __float2bfloat16(a), y = __float2bfloat16(b);
    float ra = a - __bfloat162float(x), rb = b - __bfloat162float(y);
    __nv_bfloat16 u = __float2bfloat16(ra), v = __float2bfloat16(rb);
    return ((uint32_t)*(uint16_t*)&v << 16) | *(uint16_t*)&u;
}

// ========== 128x256 HMMA GEMM core, 512 threads, 2-stage cp.async ==========
#define G2_A_BYTES 16384
#define G2_B_BYTES 32768
#define G2_STAGE   98304
#define G2_SMEM    (2 * G2_STAGE)
#define G2_THREADS 512

__device__ __forceinline__ void g256_issue(
    const __nv_bfloat16* pAh, const __nv_bfloat16* pAl,
    const __nv_bfloat16* pBh, const __nv_bfloat16* pBl,
    int kc, uint32_t stg, int tid, int K) {
    {
        const __nv_bfloat16* a0 = pAh + (size_t)kc * 64;
        const __nv_bfloat16* a1 = pAl + (size_t)kc * 64;
#pragma unroll
        for (int u = 0; u < 2; u++) {
            int idx = tid + u * 512;
            int r = idx >> 3, c = idx & 7;
            uint32_t so = SMEM_SWIZZLE_128B(r * 128 + c * 16);
            size_t go = (size_t)r * K + c * 8;
            CP_ASYNC16(stg + so, a0 + go);
            CP_ASYNC16(stg + G2_A_BYTES + so, a1 + go);
        }
    }
    {
        const __nv_bfloat16* b0 = pBh + (size_t)kc * 64;
        const __nv_bfloat16* b1 = pBl + (size_t)kc * 64;
#pragma unroll
        for (int u = 0; u < 4; u++) {
            int idx = tid + u * 512;
            int r = idx >> 3, c = idx & 7;
            uint32_t so = SMEM_SWIZZLE_128B(r * 128 + c * 16);
            size_t go = (size_t)r * K + c * 8;
            CP_ASYNC16(stg + 2 * G2_A_BYTES + so, b0 + go);
            CP_ASYNC16(stg + 2 * G2_A_BYTES + G2_B_BYTES + so, b1 + go);
        }
    }
}

// mode 1: bf16 hi/lo split; mode 2: RoPE + split (Q/K heads); mode 0: fp32
__device__ __forceinline__ void g256_core(
    const __nv_bfloat16* pAh, const __nv_bfloat16* pAl,
    const __nv_bfloat16* pBh, const __nv_bfloat16* pBl,
    int K, int N, size_t aRow, size_t bRow, int mode, int head,
    float* C, __nv_bfloat16* Ch, __nv_bfloat16* Cl, char* smem) {
    const uint32_t sb = smem_to_u32(smem);
    const int tid = threadIdx.x;
    const int wid = tid >> 5, lane = tid & 31;
    const int wm = (wid & 3) * 32;
    const int wn = (wid >> 2) * 64;
    const int a_r = lane & 15;
    const int a_k = (lane >> 4) * 8;
    const int b_kh = ((lane >> 3) & 1) * 8;
    const int b_nf = ((lane >> 4) & 1) * 8;
    const int b_r  = lane & 7;
    const int KC = K >> 6;

    float acc[2][8][4];
#pragma unroll
    for (int mt = 0; mt < 2; mt++)
#pragma unroll
        for (int nt = 0; nt < 8; nt++)
#pragma unroll
            for (int e = 0; e < 4; e++) acc[mt][nt][e] = 0.f;

    g256_issue(pAh, pAl, pBh, pBl, 0, sb, tid, K);
    CP_COMMIT();
    g256_issue(pAh, pAl, pBh, pBl, 1, sb + G2_STAGE, tid, K);
    CP_COMMIT();

    for (int kc = 0; kc < KC; kc++) {
        if (kc + 1 < KC) { CP_WAIT(1); } else { CP_WAIT(0); }
        __syncthreads();
        const uint32_t base = sb + (kc & 1) * G2_STAGE;
        const uint32_t tAh = base;
        const uint32_t tAl = base + G2_A_BYTES;
        const uint32_t tBh = base + 2 * G2_A_BYTES;
        const uint32_t tBl = base + 2 * G2_A_BYTES + G2_B_BYTES;
#pragma unroll
        for (int ks = 0; ks < 4; ks++) {
            const int k0 = ks * 16;
            uint32_t bh[8][2], bl[8][2];
#pragma unroll
            for (int np = 0; np < 4; np++) {
                int row = wn + np * 16 + b_nf + b_r;
                uint32_t off = SMEM_SWIZZLE_128B(row * 128 + (k0 + b_kh) * 2);
                ldmx4(bh[2 * np][0], bh[2 * np][1],
                      bh[2 * np + 1][0], bh[2 * np + 1][1], tBh + off);
                ldmx4(bl[2 * np][0], bl[2 * np][1],
                      bl[2 * np + 1][0], bl[2 * np + 1][1], tBl + off);
            }
#pragma unroll
            for (int mt = 0; mt < 2; mt++) {
                int rowA = wm + mt * 16 + a_r;
                uint32_t offA = SMEM_SWIZZLE_128B(rowA * 128 + (k0 + a_k) * 2);
                uint32_t a0, a1, a2, a3;
                ldmx4(a0, a1, a2, a3, tAh + offA);
#pragma unroll
                for (int nt = 0; nt < 8; nt++)
                    mma16816(acc[mt][nt][0], acc[mt][nt][1], acc[mt][nt][2],
                             acc[mt][nt][3], a0, a1, a2, a3, bh[nt][0], bh[nt][1]);
#pragma unroll
                for (int nt = 0; nt < 8; nt++)
                    mma16816(acc[mt][nt][0], acc[mt][nt][1], acc[mt][nt][2],
                             acc[mt][nt][3], a0, a1, a2, a3, bl[nt][0], bl[nt][1]);
                uint32_t l0, l1, l2, l3;
                ldmx4(l0, l1, l2, l3, tAl + offA);
#pragma unroll
                for (int nt = 0; nt < 8; nt++)
                    mma16816(acc[mt][nt][0], acc[mt][nt][1], acc[mt][nt][2],
                             acc[mt][nt][3], l0, l1, l2, l3, bh[nt][0], bh[nt][1]);
            }
        }
        __syncthreads();
        if (kc + 2 < KC) {
            g256_issue(pAh, pAl, pBh, pBl, kc + 2, sb + (kc & 1) * G2_STAGE, tid, K);
            CP_COMMIT();
        }
    }

    if (mode == 2) {
        float* st = (float*)smem;
#pragma unroll
        for (int mt = 0; mt < 2; mt++) {
            int r0 = wm + mt * 16 + (lane >> 2);
#pragma unroll
            for (int nt = 0; nt < 8; nt++) {
                int c0 = wn + nt * 8 + (lane & 3) * 2;
                st[r0 * 260 + c0]           = acc[mt][nt][0];
                st[r0 * 260 + c0 + 1]       = acc[mt][nt][1];
                st[(r0 + 8) * 260 + c0]     = acc[mt][nt][2];
                st[(r0 + 8) * 260 + c0 + 1] = acc[mt][nt][3];
            }
        }
        __syncthreads();
        const float L = 13.2877123795494f / 128.0f;
        for (int i = tid; i < 128 * 32; i += G2_THREADS) {
            int r  = i >> 5;
            int c4 = (i & 31) * 4;
            int pos = (int)((aRow + r) & (TLEN - 1));
            __nv_bfloat16 h1[4], l1[4], h2[4], l2[4];
#pragma unroll
            for (int u = 0; u < 4; u++) {
                int j = c4 + u;
                float inv = exp2f(-(float)j * L);
                float s, c;
                sincosf((float)pos * inv, &s, &c);
                float x1 = st[r * 260 + j], x2 = st[r * 260 + j + 128];
                float o1 = x1 * c - x2 * s, o2 = x2 * c + x1 * s;
                h1[u] = __float2bfloat16(o1);
                l1[u] = __float2bfloat16(o1 - __bfloat162float(h1[u]));
                h2[u] = __float2bfloat16(o2);
                l2[u] = __float2bfloat16(o2 - __bfloat162float(h2[u]));
            }
            size_t g = (aRow + r) * NQK + (size_t)head * 256 + c4;
            *(uint2*)(Ch + g)       = *(uint2*)h1;
            *(uint2*)(Cl + g)       = *(uint2*)l1;
            *(uint2*)(Ch + g + 128) = *(uint2*)h2;
            *(uint2*)(Cl + g + 128) = *(uint2*)l2;
        }
        return;
    }

#pragma unroll
    for (int mt = 0; mt < 2; mt++) {
        size_t m0 = aRow + wm + mt * 16 + (lane >> 2);
#pragma unroll
        for (int nt = 0; nt < 8; nt++) {
            size_t n0 = bRow + wn + nt * 8 + (lane & 3) * 2;
            if (mode == 1) {
                *(uint32_t*)(Ch + m0 * N + n0) = pack_hi(acc[mt][nt][0], acc[mt][nt][1]);
                *(uint32_t*)(Cl + m0 * N + n0) = pack_lo(acc[mt][nt][0], acc[mt][nt][1]);
                *(uint32_t*)(Ch + (m0 + 8) * N + n0) = pack_hi(acc[mt][nt][2], acc[mt][nt][3]);
                *(uint32_t*)(Cl + (m0 + 8) * N + n0) = pack_lo(acc[mt][nt][2], acc[mt][nt][3]);
            } else {
                *(float2*)(C + m0 * N + n0)       = make_float2(acc[mt][nt][0], acc[mt][nt][1]);
                *(float2*)(C + (m0 + 8) * N + n0) = make_float2(acc[mt][nt][2], acc[mt][nt][3]);
            }
        }
    }
}

// combined Q/K/V/G projection launch
__global__ __launch_bounds__(G2_THREADS, 1) void gemm_qkvg(
    const __nv_bfloat16* __restrict__ Xh, const __nv_bfloat16* __restrict__ Xl,
    const __nv_bfloat16* __restrict__ WqTh, const __nv_bfloat16* __restrict__ WqTl,
    const __nv_bfloat16* __restrict__ WkTh, const __nv_bfloat16* __restrict__ WkTl,
    const __nv_bfloat16* __restrict__ WvTh, const __nv_bfloat16* __restrict__ WvTl,
    const __nv_bfloat16* __restrict__ WgTh, const __nv_bfloat16* __restrict__ WgTl,
    __nv_bfloat16* __restrict__ qh, __nv_bfloat16* __restrict__ ql,
    __nv_bfloat16* __restrict__ kh, __nv_bfloat16* __restrict__ kl,
    __nv_bfloat16* __restrict__ vh, __nv_bfloat16* __restrict__ vl,
    float* __restrict__ dg) {
    extern __shared__ char smem[];
    int nb = blockIdx.x;
    const __nv_bfloat16 *Bh, *Bl;
    float* C = nullptr;
    __nv_bfloat16 *Ch = nullptr, *Cl = nullptr;
    int N, ntile, mode, head = 0;
    if (nb < 8)       { Bh = WqTh; Bl = WqTl; Ch = qh; Cl = ql; N = 2048;
                        ntile = nb; mode = 2; head = nb; }
    else if (nb < 16) { Bh = WkTh; Bl = WkTl; Ch = kh; Cl = kl; N = 2048;
                        ntile = nb - 8; mode = 2; head = nb - 8; }
    else if (nb < 32) { Bh = WvTh; Bl = WvTl; Ch = vh; Cl = vl; N = 4096;
                        ntile = nb - 16; mode = 1; }
    else              { Bh = WgTh; Bl = WgTl; C = dg; N = 4096;
                        ntile = nb - 32; mode = 0; }
    size_t aRow = (size_t)blockIdx.y * 128;
    size_t bRow = (size_t)ntile * 256;
    g256_core(Xh + aRow * HID, Xl + aRow * HID, Bh + bRow * HID, Bl + bRow * HID,
              HID, N, aRow, bRow, mode, head, C, Ch, Cl, smem);
}

// ===== Wo GEMM: tile 128x128, 256 thr, K-chunk 32, 2 CTAs/SM =====
#define W1_A     8192
#define W1_STAGE 32768
#define W1_SMEM  (2 * W1_STAGE)

__device__ __forceinline__ void wo_issue(
    const __nv_bfloat16* pAh, const __nv_bfloat16* pAl,
    const __nv_bfloat16* pBh, const __nv_bfloat16* pBl,
    int kc, uint32_t stg, int tid, int K) {
#pragma unroll
    for (int u = 0; u < 2; u++) {
        int idx = tid + u * 256;                   // 0..511
        int r = idx >> 2, c16 = (idx & 3) * 16;
        uint32_t so = r * 64 + SWZ64(r, c16);
        size_t go = (size_t)r * K + kc * 32 + (c16 >> 1);
        CP_ASYNC16(stg + so,             pAh + go);
        CP_ASYNC16(stg + W1_A + so,      pAl + go);
        CP_ASYNC16(stg + 2 * W1_A + so,  pBh + go);
        CP_ASYNC16(stg + 3 * W1_A + so,  pBl + go);
    }
}

__global__ __launch_bounds__(256, 2) void gemm_wo128(
    const __nv_bfloat16* __restrict__ Ah, const __nv_bfloat16* __restrict__ Al,
    const __nv_bfloat16* __restrict__ Bh, const __nv_bfloat16* __restrict__ Bl,
    float* __restrict__ C, int N, int K) {
    extern __shared__ char smem[];
    const uint32_t sb = smem_to_u32(smem);
    const int tid = threadIdx.x;
    const int wid = tid >> 5, lane = tid & 31;
    const int wm = (wid & 1) * 64;
    const int wn = (wid >> 1) * 32;
    const size_t aRow = (size_t)blockIdx.y * 128;
    const size_t bRow = (size_t)blockIdx.x * 128;
    const __nv_bfloat16* pAh = Ah + aRow * K;
    const __nv_bfloat16* pAl = Al + aRow * K;
    const __nv_bfloat16* pBh = Bh + bRow * K;
    const __nv_bfloat16* pBl = Bl + bRow * K;
    const int KC = K >> 5;

    const int a_r = lane & 15;
    const int a_c = (lane >> 4) * 16;
    const int b_r = lane & 7;
    const int b_c = ((lane >> 3) & 1) * 16;
    const int b_nf = ((lane >> 4) & 1) * 8;

    float acc[4][4][4];
#pragma unroll
    for (int mt = 0; mt < 4; mt++)
#pragma unroll
        for (int nt = 0; nt < 4; nt++)
#pragma unroll
            for (int e = 0; e < 4; e++) acc[mt][nt][e] = 0.f;

    wo_issue(pAh, pAl, pBh, pBl, 0, sb, tid, K);
    CP_COMMIT();
    wo_issue(pAh, pAl, pBh, pBl, 1, sb + W1_STAGE, tid, K);
    CP_COMMIT();

    for (int kc = 0; kc < KC; kc++) {
        if (kc + 1 < KC) { CP_WAIT(1); } else { CP_WAIT(0); }
        __syncthreads();
        const uint32_t base = sb + (kc & 1) * W1_STAGE;
        const uint32_t tAh = base;
        const uint32_t tAl = base + W1_A;
        const uint32_t tBh = base + 2 * W1_A;
        const uint32_t tBl = base + 3 * W1_A;
#pragma unroll
        for (int ks = 0; ks < 2; ks++) {
            const int kb = ks * 32;
            uint32_t bh[4][2], bl[4][2];
#pragma unroll
            for (int np = 0; np < 2; np++) {
                int row = wn + np * 16 + b_nf + b_r;
                uint32_t off = row * 64 + SWZ64(row, kb + b_c);
                ldmx4(bh[2 * np][0], bh[2 * np][1],
                      bh[2 * np + 1][0], bh[2 * np + 1][1], tBh + off);
                ldmx4(bl[2 * np][0], bl[2 * np][1],
                      bl[2 * np + 1][0], bl[2 * np + 1][1], tBl + off);
            }
#pragma unroll
            for (int mt = 0; mt < 4; mt++) {
                int rowA = wm + mt * 16 + a_r;
                uint32_t offA = rowA * 64 + SWZ64(rowA, kb + a_c);
                uint32_t a0, a1, a2, a3;
                ldmx4(a0, a1, a2, a3, tAh + offA);
#pragma unroll
                for (int nt = 0; nt < 4; nt++)
                    mma16816(acc[mt][nt][0], acc[mt][nt][1], acc[mt][nt][2],
                             acc[mt][nt][3], a0, a1, a2, a3, bh[nt][0], bh[nt][1]);
#pragma unroll
                for (int nt = 0; nt < 4; nt++)
                    mma16816(acc[mt][nt][0], acc[mt][nt][1], acc[mt][nt][2],
                             acc[mt][nt][3], a0, a1, a2, a3, bl[nt][0], bl[nt][1]);
                uint32_t l0, l1, l2, l3;
                ldmx4(l0, l1, l2, l3, tAl + offA);
#pragma unroll
                for (int nt = 0; nt < 4; nt++)
                    mma16816(acc[mt][nt][0], acc[mt][nt][1], acc[mt][nt][2],
                             acc[mt][nt][3], l0, l1, l2, l3, bh[nt][0], bh[nt][1]);
            }
        }
        __syncthreads();
        if (kc + 2 < KC) {
            wo_issue(pAh, pAl, pBh, pBl, kc + 2, sb + (kc & 1) * W1_STAGE, tid, K);
            CP_COMMIT();
        }
    }

#pragma unroll
    for (int mt = 0; mt < 4; mt++) {
        size_t m0 = aRow + wm + mt * 16 + (lane >> 2);
#pragma unroll
        for (int nt = 0; nt < 4; nt++) {
            size_t n0 = bRow + wn + nt * 8 + (lane & 3) * 2;
            *(float2*)(C + m0 * N + n0)       = make_float2(acc[mt][nt][0], acc[mt][nt][1]);
            *(float2*)(C + (m0 + 8) * N + n0) = make_float2(acc[mt][nt][2], acc[mt][nt][3]);
        }
    }
}

// ------------- prep: 5 weight transposes + X split, one launch -------------
__global__ __launch_bounds__(256) void prep_all(
    const float* __restrict__ X,
    const float* __restrict__ Wq, const float* __restrict__ Wk,
    const float* __restrict__ Wv, const float* __restrict__ Wg,
    const float* __restrict__ Wo,
    __nv_bfloat16* __restrict__ Xh, __nv_bfloat16* __restrict__ Xl,
    __nv_bfloat16* __restrict__ WqTh, __nv_bfloat16* __restrict__ WqTl,
    __nv_bfloat16* __restrict__ WkTh, __nv_bfloat16* __restrict__ WkTl,
    __nv_bfloat16* __restrict__ WvTh, __nv_bfloat16* __restrict__ WvTl,
    __nv_bfloat16* __restrict__ WgTh, __nv_bfloat16* __restrict__ WgTl,
    __nv_bfloat16* __restrict__ WoTh, __nv_bfloat16* __restrict__ WoTl) {
    int id = blockIdx.x;
    if (id >= 32768) {
        int i = ((id - 32768) * 256 + threadIdx.x) * 4;
        float4 v = *(const float4*)(X + i);
        *(uint2*)(Xh + i) = make_uint2(pack_hi(v.x, v.y), pack_hi(v.z, v.w));
        *(uint2*)(Xl + i) = make_uint2(pack_lo(v.x, v.y), pack_lo(v.z, v.w));
        return;
    }
    __shared__ float ts[32][33];
    const float* in;
    __nv_bfloat16 *hT, *lT;
    int K, N, local;
    if (id < 4096)       { in = Wq; hT = WqTh; lT = WqTl; K = 2048; N = 2048; local = id; }
    else if (id < 8192)  { in = Wk; hT = WkTh; lT = WkTl; K = 2048; N = 2048; local = id - 4096; }
    else if (id < 16384) { in = Wv; hT = WvTh; lT = WvTl; K = 2048; N = 4096; local = id - 8192; }
    else if (id < 24576) { in = Wg; hT = WgTh; lT = WgTl; K = 2048; N = 4096; local = id - 16384; }
    else                 { in = Wo; hT = WoTh; lT = WoTl; K = 4096; N = 2048; local = id - 24576; }
    int nt = local % (N >> 5), kt = local / (N >> 5);
    int n0 = nt * 32, k0 = kt * 32;
    int tx = threadIdx.x & 31, ty = threadIdx.x >> 5;
#pragma unroll
    for (int r = 0; r < 4; r++)
        ts[ty + r * 8][tx] = in[(size_t)(k0 + ty + r * 8) * N + n0 + tx];
    __syncthreads();
#pragma unroll
    for (int r = 0; r < 4; r++) {
        int n = n0 + ty + r * 8, kk = k0 + tx;
        float x = ts[tx][ty + r * 8];
        __nv_bfloat16 hi = __float2bfloat16(x);
        hT[(size_t)n * K + kk] = hi;
        lT[(size_t)n * K + kk] = __float2bfloat16(x - __bfloat162float(hi));
    }
}

// ============ Tensor-core retention: i64 x j64, fused RMS+gate epilogue ============
#define RQh  0
#define RQl  32768
#define RKh  65536
#define RKl  98304
#define RV0h 131072
#define RV0l 147456
#define RV1h 163840
#define RV1l 180224
#define RSh  196608
#define RSl  204800
#define RET_TC_SMEM 212992

__device__ __forceinline__ void ret_issue_K64(uint32_t sb, int tid,
                                              const __nv_bfloat16* Kh,
                                              const __nv_bfloat16* Kl, size_t kb) {
#pragma unroll
    for (int u = 0; u < 4; u++) {
        int idx = tid + u * 512;
        int r = idx >> 5, c16 = (idx & 31) * 16;
        uint32_t so = r * 512 + ROWSWZ(r, c16);
        size_t ga = kb + (size_t)r * NQK + (c16 >> 1);
        CP_ASYNC16(sb + RKh + so, Kh + ga);
        CP_ASYNC16(sb + RKl + so, Kl + ga);
    }
}
__device__ __forceinline__ void ret_issue_V(uint32_t sb, int tid,
                                            const __nv_bfloat16* Vh,
                                            const __nv_bfloat16* Vl,
                                            size_t vbase, int grow,
                                            uint32_t bufh, uint32_t bufl) {
#pragma unroll
    for (int u = 0; u < 2; u++) {
        int idx = tid + u * 512;
        int r = idx >> 6, c16 = (idx & 63) * 16;
        uint32_t so = r * 1024 + ROWSWZ(r, c16);
        size_t ga = vbase + (size_t)(grow + r) * NVG + (c16 >> 1);
        CP_ASYNC16(sb + bufh + so, Vh + ga);
        CP_ASYNC16(sb + bufl + so, Vl + ga);
    }
}
__device__ __forceinline__ void ret_sv_phase(uint32_t sb, int lane, int wm, int wn,
                                             int p, uint32_t vbh, uint32_t vbl,
                                             float accO[16][4]) {
    const int ar = wm * 16 + (lane & 15);
    const int akb = (lane >> 4) * 16;
    uint32_t aoff = ar * 128 + ROWSWZ(ar, p * 32 + akb);
    uint32_t s0, s1, s2, s3, t0, t1, t2, t3;
    ldmx4(s0, s1, s2, s3, sb + RSh + aoff);
    ldmx4(t0, t1, t2, t3, sb + RSl + aoff);
    const int vr = lane & 15;
    const int vc = (lane >> 4) * 8;
#pragma unroll
    for (int nfp = 0; nfp < 8; nfp++) {
        uint32_t voff = vr * 1024 + ROWSWZ(vr, (wn * 128 + nfp * 16 + vc) * 2);
        uint32_t v0, v1, v2, v3, u0, u1, u2, u3;
        ldmx4t(v0, v1, v2, v3, sb + vbh + voff);
        mma16816(accO[2 * nfp][0], accO[2 * nfp][1], accO[2 * nfp][2],
                 accO[2 * nfp][3], s0, s1, s2, s3, v0, v1);
        mma16816(accO[2 * nfp + 1][0], accO[2 * nfp + 1][1], accO[2 * nfp + 1][2],
                 accO[2 * nfp + 1][3], s0, s1, s2, s3, v2, v3);
        ldmx4t(u0, u1, u2, u3, sb + vbl + voff);
        mma16816(accO[2 * nfp][0], accO[2 * nfp][1], accO[2 * nfp][2],
                 accO[2 * nfp][3], s0, s1, s2, s3, u0, u1);
        mma16816(accO[2 * nfp + 1][0], accO[2 * nfp + 1][1], accO[2 * nfp + 1][2],
                 accO[2 * nfp + 1][3], s0, s1, s2, s3, u2, u3);
        mma16816(accO[2 * nfp][0], accO[2 * nfp][1], accO[2 * nfp][2],
                 accO[2 * nfp][3], t0, t1, t2, t3, v0, v1);
        mma16816(accO[2 * nfp + 1][0], accO[2 * nfp + 1][1], accO[2 * nfp + 1][2],
                 accO[2 * nfp + 1][3], t0, t1, t2, t3, v2, v3);
    }
}

__global__ __launch_bounds__(512, 1) void retention_tc(
    const __nv_bfloat16* __restrict__ Qh, const __nv_bfloat16* __restrict__ Ql,
    const __nv_bfloat16* __restrict__ Kh, const __nv_bfloat16* __restrict__ Kl,
    const __nv_bfloat16* __restrict__ Vh, const __nv_bfloat16* __restrict__ Vl,
    const float* __restrict__ dg, const float* __restrict__ gw,
    __nv_bfloat16* __restrict__ Oh, __nv_bfloat16* __restrict__ Ol) {
    extern __shared__ char smem[];
    const uint32_t sb = smem_to_u32(smem);
    const int tid  = threadIdx.x;
    const int wid  = tid >> 5, lane = tid & 31;
    const int wm   = wid & 3;
    const int wn   = wid >> 2;

    const int it = 31 - blockIdx.x;
    const int h  = blockIdx.y;
    const int b  = blockIdx.z;
    const int i0 = it * 64;
    const float scale = 0.0625f;
    const float gamma = 1.0f - exp2f(-5.0f - (float)h);
    const float l2g   = log2f(gamma);

    const size_t kbase = (size_t)(b * TLEN) * NQK + h * DKh;
    const size_t vbase = (size_t)(b * TLEN) * NVG + h * DVh;

    int jt0 = 0;
    {
        float Dh = -24.0f / l2g;
        int jlow = i0 - 63 - (int)Dh;
        if (jlow > 0) jt0 = jlow >> 6;
    }
    const int jtmax = it;
    const int phmax = jtmax * 4 + 3;

    {
        const size_t qb = (size_t)(b * TLEN + i0) * NQK + h * DKh;
#pragma unroll
        for (int u = 0; u < 4; u++) {
            int idx = tid + u * 512;
            int r = idx >> 5, c16 = (idx & 31) * 16;
            uint32_t so = r * 512 + ROWSWZ(r, c16);
            size_t ga = qb + (size_t)r * NQK + (c16 >> 1);
            CP_ASYNC16(sb + RQh + so, Qh + ga);
            CP_ASYNC16(sb + RQl + so, Ql + ga);
        }
        ret_issue_K64(sb, tid, Kh, Kl, kbase + (size_t)(jt0 * 64) * NQK);
        CP_COMMIT();
        ret_issue_V(sb, tid, Vh, Vl, vbase, jt0 * 64,      RV0h, RV0l);
        CP_COMMIT();
        ret_issue_V(sb, tid, Vh, Vl, vbase, jt0 * 64 + 16, RV1h, RV1l);
        CP_COMMIT();
    }

    float accO[16][4];
#pragma unroll
    for (int nf = 0; nf < 16; nf++)
#pragma unroll
        for (int e = 0; e < 4; e++) accO[nf][e] = 0.f;

    for (int jt = jt0; jt <= jtmax; jt++) {
        const int j0 = jt * 64;
        const int jn = (jt + 1 <= jtmax) ? (jt + 1) : jtmax;
        const int phb = jt * 4 + 2;

        CP_WAIT(2);
        __syncthreads();

        float accS[2][4];
#pragma unroll
        for (int nf = 0; nf < 2; nf++)
#pragma unroll
            for (int e = 0; e < 4; e++) accS[nf][e] = 0.f;
        {
            const int ar = wm * 16 + (lane & 15);
            const int akb = (lane >> 4) * 16;
            const int kb_r = lane & 7;
            const int kb_kh = ((lane >> 3) & 1) * 8;
            const int kb_nf = ((lane >> 4) & 1) * 8;
#pragma unroll
            for (int ks = 0; ks < 16; ks++) {
                uint32_t aoff = ar * 512 + ROWSWZ(ar, ks * 32 + akb);
                uint32_t a0, a1, a2, a3, l0, l1, l2, l3;
                ldmx4(a0, a1, a2, a3, sb + RQh + aoff);
                ldmx4(l0, l1, l2, l3, sb + RQl + aoff);
                int brow = wn * 16 + kb_nf + kb_r;
                uint32_t boff = brow * 512 + ROWSWZ(brow, ks * 32 + kb_kh * 2);
                uint32_t kb0, kb1, kb2, kb3, kc0, kc1, kc2, kc3;
                ldmx4(kb0, kb1, kb2, kb3, sb + RKh + boff);
                mma16816(accS[0][0], accS[0][1], accS[0][2], accS[0][3],
                         a0, a1, a2, a3, kb0, kb1);
                mma16816(accS[1][0], accS[1][1], accS[1][2], accS[1][3],
                         a0, a1, a2, a3, kb2, kb3);
                ldmx4(kc0, kc1, kc2, kc3, sb + RKl + boff);
                mma16816(accS[0][0], accS[0][1], accS[0][2], accS[0][3],
                         a0, a1, a2, a3, kc0, kc1);
                mma16816(accS[1][0], accS[1][1], accS[1][2], accS[1][3],
                         a0, a1, a2, a3, kc2, kc3);
                mma16816(accS[0][0], accS[0][1], accS[0][2], accS[0][3],
                         l0, l1, l2, l3, kb0, kb1);
                mma16816(accS[1][0], accS[1][1], accS[1][2], accS[1][3],
                         l0, l1, l2, l3, kb2, kb3);
            }
        }
        {
            const int il = wm * 16 + (lane >> 2);
#pragma unroll
            for (int nf = 0; nf < 2; nf++) {
                int jl = wn * 16 + nf * 8 + (lane & 3) * 2;
#pragma unroll
                for (int half = 0; half < 2; half++) {
                    int r = il + half * 8;
                    int d0 = (i0 + r) - (j0 + jl);
                    int d1 = d0 - 1;
                    float w0 = (d0 >= 0) ? scale * exp2f(l2g * (float)d0) : 0.f;
                    float w1 = (d1 >= 0) ? scale * exp2f(l2g * (float)d1) : 0.f;
                    float s0 = accS[nf][half * 2 + 0] * w0;
                    float s1 = accS[nf][half * 2 + 1] * w1;
                    uint32_t so = r * 128 + ROWSWZ(r, jl * 2);
                    *(uint32_t*)(smem + RSh + so) = pack_hi(s0, s1);
                    *(uint32_t*)(smem + RSl + so) = pack_lo(s0, s1);
                }
            }
        }
        __syncthreads();
        ret_issue_K64(sb, tid, Kh, Kl, kbase + (size_t)(jn * 64) * NQK);
        CP_COMMIT();

#pragma unroll
        for (int p = 0; p < 4; p++) {
            if (p < 2) { CP_WAIT(2); } else { CP_WAIT(1); }
            __syncthreads();
            uint32_t bh_ = (p & 1) ? RV1h : RV0h;
            uint32_t bl_ = (p & 1) ? RV1l : RV0l;
            ret_sv_phase(sb, lane, wm, wn, p, bh_, bl_, accO);
            __syncthreads();
            int ph2 = phb + p;
            if (ph2 > phmax) ph2 = phmax;
            ret_issue_V(sb, tid, Vh, Vl, vbase, ph2 * 16, bh_, bl_);
            CP_COMMIT();
        }
    }
    CP_WAIT(0);
    __syncthreads();

    // ---- fused epilogue: RMS over DV=512 + SiLU gate + hi/lo split ----
    {
        float ss0 = 0.f, ss1 = 0.f;
#pragma unroll
        for (int nf = 0; nf < 16; nf++) {
            ss0 += accO[nf][0] * accO[nf][0] + accO[nf][1] * accO[nf][1];
            ss1 += accO[nf][2] * accO[nf][2] + accO[nf][3] * accO[nf][3];
        }
        ss0 += __shfl_xor_sync(0xFFFFFFFFu, ss0, 1);
        ss0 += __shfl_xor_sync(0xFFFFFFFFu, ss0, 2);
        ss1 += __shfl_xor_sync(0xFFFFFFFFu, ss1, 1);
        ss1 += __shfl_xor_sync(0xFFFFFFFFu, ss1, 2);

        float* rs = (float*)smem;
        const int r0 = wm * 16 + (lane >> 2);
        if ((lane & 3) == 0) {
            rs[r0 * 4 + wn]       = ss0;
            rs[(r0 + 8) * 4 + wn] = ss1;
        }
        __syncthreads();
        float tot0 = rs[r0 * 4 + 0] + rs[r0 * 4 + 1] + rs[r0 * 4 + 2] + rs[r0 * 4 + 3];
        float tot1 = rs[(r0 + 8) * 4 + 0] + rs[(r0 + 8) * 4 + 1]
                   + rs[(r0 + 8) * 4 + 2] + rs[(r0 + 8) * 4 + 3];
        float rms0 = rsqrtf(tot0 * (1.0f / 512.0f) + 1e-5f);
        float rms1 = rsqrtf(tot1 * (1.0f / 512.0f) + 1e-5f);

        size_t row0 = (size_t)(b * TLEN + i0 + r0);
        size_t row1 = row0 + 8;
#pragma unroll
        for (int nf = 0; nf < 16; nf++) {
            int cl = wn * 128 + nf * 8 + (lane & 3) * 2;
            size_t col = (size_t)h * DVh + cl;
            float w0 = gw[cl], w1 = gw[cl + 1];
            float g00 = dg[row0 * NVG + col], g01 = dg[row0 * NVG + col + 1];
            float g10 = dg[row1 * NVG + col], g11 = dg[row1 * NVG + col + 1];
            float o00 = accO[nf][0] * rms0 * w0 * (g00 / (1.f + expf(-g00)));
            float o01 = accO[nf][1] * rms0 * w1 * (g01 / (1.f + expf(-g01)));
            float o10 = accO[nf][2] * rms1 * w0 * (g10 / (1.f + expf(-g10)));
            float o11 = accO[nf][3] * rms1 * w1 * (g11 / (1.f + expf(-g11)));
            *(uint32_t*)(Oh + row0 * NVG + col) = pack_hi(o00, o01);
            *(uint32_t*)(Ol + row0 * NVG + col) = pack_lo(o00, o01);
            *(uint32_t*)(Oh + row1 * NVG + col) = pack_hi(o10, o11);
            *(uint32_t*)(Ol + row1 * NVG + col) = pack_lo(o10, o11);
        }
    }
}

extern "C" void kernel_launch(void* const* d_in, const int* in_sizes, int n_in,
                              void* d_out, int out_size) {
    const float* X   = (const float*)d_in[0];
    const float* Wq  = (const float*)d_in[1];
    const float* Wk  = (const float*)d_in[2];
    const float* Wv  = (const float*)d_in[3];
    const float* Wg  = (const float*)d_in[4];
    const float* Wo  = (const float*)d_in[5];
    const float* gnw = (const float*)d_in[6];
    float* out = (float*)d_out;

    unsigned char* pool = nullptr;
    cudaGetSymbolAddress((void**)&pool, g_pool);

    float* dq  = (float*)pool;
    float* dk  = dq  + 8388608;
    float* dv  = dk  + 8388608;
    float* dg  = dv  + 16777216;
    float* dro = dg  + 16777216;
    __nv_bfloat16* bf = (__nv_bfloat16*)(dro + 16777216);
    __nv_bfloat16* Xh   = bf;             __nv_bfloat16* Xl   = Xh   + 8388608;
    __nv_bfloat16* WqTh = Xl   + 8388608; __nv_bfloat16* WqTl = WqTh + 4194304;
    __nv_bfloat16* WkTh = WqTl + 4194304; __nv_bfloat16* WkTl = WkTh + 4194304;
    __nv_bfloat16* WvTh = WkTl + 4194304; __nv_bfloat16* WvTl = WvTh + 8388608;
    __nv_bfloat16* WgTh = WvTl + 8388608; __nv_bfloat16* WgTl = WgTh + 8388608;
    __nv_bfloat16* WoTh = WgTl + 8388608; __nv_bfloat16* WoTl = WoTh + 8388608;
    __nv_bfloat16* droH = WoTl + 8388608; __nv_bfloat16* droL = droH + 16777216;
    __nv_bfloat16* qh   = droL + 16777216; __nv_bfloat16* ql = qh + 8388608;
    __nv_bfloat16* kh   = ql + 8388608;    __nv_bfloat16* kl = kh + 8388608;
    __nv_bfloat16* vh   = kl + 8388608;    __nv_bfloat16* vl = vh + 16777216;

    cudaFuncSetAttribute(gemm_qkvg, cudaFuncAttributeMaxDynamicSharedMemorySize, G2_SMEM);
    cudaFuncSetAttribute(gemm_wo128, cudaFuncAttributeMaxDynamicSharedMemorySize, W1_SMEM);
    cudaFuncSetAttribute(retention_tc, cudaFuncAttributeMaxDynamicSharedMemorySize,
                         RET_TC_SMEM);

    dim3 thr(256);
    prep_all<<<40960, thr>>>(X, Wq, Wk, Wv, Wg, Wo, Xh, Xl,
                             WqTh, WqTl, WkTh, WkTl, WvTh, WvTl,
                             WgTh, WgTl, WoTh, WoTl);

    gemm_qkvg<<<dim3(48, 32), dim3(G2_THREADS), G2_SMEM>>>(
        Xh, Xl, WqTh, WqTl, WkTh, WkTl, WvTh, WvTl, WgTh, WgTl,
        qh, ql, kh, kl, vh, vl, dg);

    retention_tc<<<dim3(32, HQ, 2), dim3(512), RET_TC_SMEM>>>(
        qh, ql, kh, kl, vh, vl, dg, gnw, droH, droL);

    gemm_wo128<<<dim3(16, 32), thr, W1_SMEM>>>(droH, droL, WoTh, WoTl,
                                               out, HID, NVG);
}

// round 17
// speedup vs baseline: 1.0034x; 1.0034x over previous
#include <cuda_runtime.h>
#include <cuda_bf16.h>
#include <stdint.h>
#include <cstdint>
#include <math.h>

#define MTOT 4096      // B*T
#define TLEN 2048
#define HQ   8
#define DKh  256
#define DVh  512
#define HID  2048
#define NQK  2048      // H*DK
#define NVG  4096      // H*DV

__device__ __align__(1024) unsigned char g_pool[637534208];

__device__ __forceinline__ uint32_t smem_to_u32(const void* p) {
    uint32_t a;
    asm("{ .reg .u64 t; cvta.to.shared.u64 t, %1; cvt.u32.u64 %0, t; }"
        : "=r"(a) : "l"(p));
    return a;
}
#define SMEM_SWIZZLE_128B(byte_offset) \
    ((byte_offset) ^ (((byte_offset) >> 3) & 0x70))
#define ROWSWZ(row, c2) ((c2) ^ (((row) & 7) << 4))

#define CP_ASYNC16(dst_u32, gptr) \
    asm volatile("cp.async.cg.shared.global [%0], [%1], 16;" \
                 :: "r"(dst_u32), "l"(gptr))
#define CP_COMMIT() asm volatile("cp.async.commit_group;" ::: "memory")
#define CP_WAIT(n)  asm volatile("cp.async.wait_group %0;" :: "n"(n) : "memory")

// -------- mma.sync / ldmatrix helpers --------
__device__ __forceinline__ void ldmx4(uint32_t& r0, uint32_t& r1, uint32_t& r2,
                                      uint32_t& r3, uint32_t addr) {
    asm volatile("ldmatrix.sync.aligned.m8n8.x4.shared.b16 {%0,%1,%2,%3}, [%4];"
                 : "=r"(r0), "=r"(r1), "=r"(r2), "=r"(r3) : "r"(addr));
}
__device__ __forceinline__ void ldmx4t(uint32_t& r0, uint32_t& r1, uint32_t& r2,
                                       uint32_t& r3, uint32_t addr) {
    asm volatile("ldmatrix.sync.aligned.m8n8.x4.trans.shared.b16 {%0,%1,%2,%3}, [%4];"
                 : "=r"(r0), "=r"(r1), "=r"(r2), "=r"(r3) : "r"(addr));
}
__device__ __forceinline__ void mma16816(float& c0, float& c1, float& c2, float& c3,
                                         uint32_t a0, uint32_t a1, uint32_t a2,
                                         uint32_t a3, uint32_t b0, uint32_t b1) {
    asm volatile(
        "mma.sync.aligned.m16n8k16.row.col.f32.bf16.bf16.f32 "
        "{%0,%1,%2,%3}, {%4,%5,%6,%7}, {%8,%9}, {%0,%1,%2,%3};"
        : "+f"(c0), "+f"(c1), "+f"(c2), "+f"(c3)
        : "r"(a0), "r"(a1), "r"(a2), "r"(a3), "r"(b0), "r"(b1));
}
__device__ __forceinline__ uint32_t pack_hi(float a, float b) {
    __nv_bfloat16 x = __float2bfloat16(a), y = __float2bfloat16(b);
    return ((uint32_t)*(uint16_t*)&y << 16) | *(uint16_t*)&x;
}
__device__ __forceinline__ uint32_t pack_lo(float a, float b) {
    __nv_bfloat16 x = __float2bfloat16(a), y = __float2bfloat16(b);
    float ra = a - __bfloat162float(x), rb = b - __bfloat162float(y);
    __nv_bfloat16 u = __float2bfloat16(ra), v = __float2bfloat16(rb);
    return ((uint32_t)*(uint16_t*)&v << 16) | *(uint16_t*)&u;
}

// ========== 128x256 HMMA GEMM core, 512 threads, 2-stage cp.async ==========
#define G2_A_BYTES 16384
#define G2_B_BYTES 32768
#define G2_STAGE   98304
#define G2_SMEM    (2 * G2_STAGE)
#define G2_THREADS 512

__device__ __forceinline__ void g256_issue(
    const __nv_bfloat16* pAh, const __nv_bfloat16* pAl,
    const __nv_bfloat16* pBh, const __nv_bfloat16* pBl,
    int kc, uint32_t stg, int tid, int K) {
    {
        const __nv_bfloat16* a0 = pAh + (size_t)kc * 64;
        const __nv_bfloat16* a1 = pAl + (size_t)kc * 64;
#pragma unroll
        for (int u = 0; u < 2; u++) {
            int idx = tid + u * 512;
            int r = idx >> 3, c = idx & 7;
            uint32_t so = SMEM_SWIZZLE_128B(r * 128 + c * 16);
            size_t go = (size_t)r * K + c * 8;
            CP_ASYNC16(stg + so, a0 + go);
            CP_ASYNC16(stg + G2_A_BYTES + so, a1 + go);
        }
    }
    {
        const __nv_bfloat16* b0 = pBh + (size_t)kc * 64;
        const __nv_bfloat16* b1 = pBl + (size_t)kc * 64;
#pragma unroll
        for (int u = 0; u < 4; u++) {
            int idx = tid + u * 512;
            int r = idx >> 3, c = idx & 7;
            uint32_t so = SMEM_SWIZZLE_128B(r * 128 + c * 16);
            size_t go = (size_t)r * K + c * 8;
            CP_ASYNC16(stg + 2 * G2_A_BYTES + so, b0 + go);
            CP_ASYNC16(stg + 2 * G2_A_BYTES + G2_B_BYTES + so, b1 + go);
        }
    }
}

// mode 0: fp32 C; mode 1: bf16 hi/lo split; mode 2: RoPE + split (Q/K heads)
__device__ __forceinline__ void g256_core(
    const __nv_bfloat16* pAh, const __nv_bfloat16* pAl,
    const __nv_bfloat16* pBh, const __nv_bfloat16* pBl,
    int K, int N, size_t aRow, size_t bRow, int mode, int head,
    float* C, __nv_bfloat16* Ch, __nv_bfloat16* Cl, char* smem) {
    const uint32_t sb = smem_to_u32(smem);
    const int tid = threadIdx.x;
    const int wid = tid >> 5, lane = tid & 31;
    const int wm = (wid & 3) * 32;
    const int wn = (wid >> 2) * 64;
    const int a_r = lane & 15;
    const int a_k = (lane >> 4) * 8;
    const int b_kh = ((lane >> 3) & 1) * 8;
    const int b_nf = ((lane >> 4) & 1) * 8;
    const int b_r  = lane & 7;
    const int KC = K >> 6;

    float acc[2][8][4];
#pragma unroll
    for (int mt = 0; mt < 2; mt++)
#pragma unroll
        for (int nt = 0; nt < 8; nt++)
#pragma unroll
            for (int e = 0; e < 4; e++) acc[mt][nt][e] = 0.f;

    g256_issue(pAh, pAl, pBh, pBl, 0, sb, tid, K);
    CP_COMMIT();
    g256_issue(pAh, pAl, pBh, pBl, 1, sb + G2_STAGE, tid, K);
    CP_COMMIT();

    for (int kc = 0; kc < KC; kc++) {
        if (kc + 1 < KC) { CP_WAIT(1); } else { CP_WAIT(0); }
        __syncthreads();
        const uint32_t base = sb + (kc & 1) * G2_STAGE;
        const uint32_t tAh = base;
        const uint32_t tAl = base + G2_A_BYTES;
        const uint32_t tBh = base + 2 * G2_A_BYTES;
        const uint32_t tBl = base + 2 * G2_A_BYTES + G2_B_BYTES;
#pragma unroll
        for (int ks = 0; ks < 4; ks++) {
            const int k0 = ks * 16;
            uint32_t bh[8][2], bl[8][2];
#pragma unroll
            for (int np = 0; np < 4; np++) {
                int row = wn + np * 16 + b_nf + b_r;
                uint32_t off = SMEM_SWIZZLE_128B(row * 128 + (k0 + b_kh) * 2);
                ldmx4(bh[2 * np][0], bh[2 * np][1],
                      bh[2 * np + 1][0], bh[2 * np + 1][1], tBh + off);
                ldmx4(bl[2 * np][0], bl[2 * np][1],
                      bl[2 * np + 1][0], bl[2 * np + 1][1], tBl + off);
            }
#pragma unroll
            for (int mt = 0; mt < 2; mt++) {
                int rowA = wm + mt * 16 + a_r;
                uint32_t offA = SMEM_SWIZZLE_128B(rowA * 128 + (k0 + a_k) * 2);
                uint32_t a0, a1, a2, a3;
                ldmx4(a0, a1, a2, a3, tAh + offA);
#pragma unroll
                for (int nt = 0; nt < 8; nt++)
                    mma16816(acc[mt][nt][0], acc[mt][nt][1], acc[mt][nt][2],
                             acc[mt][nt][3], a0, a1, a2, a3, bh[nt][0], bh[nt][1]);
#pragma unroll
                for (int nt = 0; nt < 8; nt++)
                    mma16816(acc[mt][nt][0], acc[mt][nt][1], acc[mt][nt][2],
                             acc[mt][nt][3], a0, a1, a2, a3, bl[nt][0], bl[nt][1]);
                uint32_t l0, l1, l2, l3;
                ldmx4(l0, l1, l2, l3, tAl + offA);
#pragma unroll
                for (int nt = 0; nt < 8; nt++)
                    mma16816(acc[mt][nt][0], acc[mt][nt][1], acc[mt][nt][2],
                             acc[mt][nt][3], l0, l1, l2, l3, bh[nt][0], bh[nt][1]);
            }
        }
        __syncthreads();
        if (kc + 2 < KC) {
            g256_issue(pAh, pAl, pBh, pBl, kc + 2, sb + (kc & 1) * G2_STAGE, tid, K);
            CP_COMMIT();
        }
    }

    if (mode == 2) {
        float* st = (float*)smem;
#pragma unroll
        for (int mt = 0; mt < 2; mt++) {
            int r0 = wm + mt * 16 + (lane >> 2);
#pragma unroll
            for (int nt = 0; nt < 8; nt++) {
                int c0 = wn + nt * 8 + (lane & 3) * 2;
                st[r0 * 260 + c0]           = acc[mt][nt][0];
                st[r0 * 260 + c0 + 1]       = acc[mt][nt][1];
                st[(r0 + 8) * 260 + c0]     = acc[mt][nt][2];
                st[(r0 + 8) * 260 + c0 + 1] = acc[mt][nt][3];
            }
        }
        __syncthreads();
        const float L = 13.2877123795494f / 128.0f;
        for (int i = tid; i < 128 * 32; i += G2_THREADS) {
            int r  = i >> 5;
            int c4 = (i & 31) * 4;
            int pos = (int)((aRow + r) & (TLEN - 1));
            __nv_bfloat16 h1[4], l1[4], h2[4], l2[4];
#pragma unroll
            for (int u = 0; u < 4; u++) {
                int j = c4 + u;
                float inv = exp2f(-(float)j * L);
                float s, c;
                sincosf((float)pos * inv, &s, &c);
                float x1 = st[r * 260 + j], x2 = st[r * 260 + j + 128];
                float o1 = x1 * c - x2 * s, o2 = x2 * c + x1 * s;
                h1[u] = __float2bfloat16(o1);
                l1[u] = __float2bfloat16(o1 - __bfloat162float(h1[u]));
                h2[u] = __float2bfloat16(o2);
                l2[u] = __float2bfloat16(o2 - __bfloat162float(h2[u]));
            }
            size_t g = (aRow + r) * NQK + (size_t)head * 256 + c4;
            *(uint2*)(Ch + g)       = *(uint2*)h1;
            *(uint2*)(Cl + g)       = *(uint2*)l1;
            *(uint2*)(Ch + g + 128) = *(uint2*)h2;
            *(uint2*)(Cl + g + 128) = *(uint2*)l2;
        }
        return;
    }

#pragma unroll
    for (int mt = 0; mt < 2; mt++) {
        size_t m0 = aRow + wm + mt * 16 + (lane >> 2);
#pragma unroll
        for (int nt = 0; nt < 8; nt++) {
            size_t n0 = bRow + wn + nt * 8 + (lane & 3) * 2;
            if (mode == 1) {
                *(uint32_t*)(Ch + m0 * N + n0) = pack_hi(acc[mt][nt][0], acc[mt][nt][1]);
                *(uint32_t*)(Cl + m0 * N + n0) = pack_lo(acc[mt][nt][0], acc[mt][nt][1]);
                *(uint32_t*)(Ch + (m0 + 8) * N + n0) = pack_hi(acc[mt][nt][2], acc[mt][nt][3]);
                *(uint32_t*)(Cl + (m0 + 8) * N + n0) = pack_lo(acc[mt][nt][2], acc[mt][nt][3]);
            } else {
                *(float2*)(C + m0 * N + n0)       = make_float2(acc[mt][nt][0], acc[mt][nt][1]);
                *(float2*)(C + (m0 + 8) * N + n0) = make_float2(acc[mt][nt][2], acc[mt][nt][3]);
            }
        }
    }
}

// combined Q/K/V/G projection launch
__global__ __launch_bounds__(G2_THREADS, 1) void gemm_qkvg(
    const __nv_bfloat16* __restrict__ Xh, const __nv_bfloat16* __restrict__ Xl,
    const __nv_bfloat16* __restrict__ WqTh, const __nv_bfloat16* __restrict__ WqTl,
    const __nv_bfloat16* __restrict__ WkTh, const __nv_bfloat16* __restrict__ WkTl,
    const __nv_bfloat16* __restrict__ WvTh, const __nv_bfloat16* __restrict__ WvTl,
    const __nv_bfloat16* __restrict__ WgTh, const __nv_bfloat16* __restrict__ WgTl,
    __nv_bfloat16* __restrict__ qh, __nv_bfloat16* __restrict__ ql,
    __nv_bfloat16* __restrict__ kh, __nv_bfloat16* __restrict__ kl,
    __nv_bfloat16* __restrict__ vh, __nv_bfloat16* __restrict__ vl,
    float* __restrict__ dg) {
    extern __shared__ char smem[];
    int nb = blockIdx.x;
    const __nv_bfloat16 *Bh, *Bl;
    float* C = nullptr;
    __nv_bfloat16 *Ch = nullptr, *Cl = nullptr;
    int N, ntile, mode, head = 0;
    if (nb < 8)       { Bh = WqTh; Bl = WqTl; Ch = qh; Cl = ql; N = 2048;
                        ntile = nb; mode = 2; head = nb; }
    else if (nb < 16) { Bh = WkTh; Bl = WkTl; Ch = kh; Cl = kl; N = 2048;
                        ntile = nb - 8; mode = 2; head = nb - 8; }
    else if (nb < 32) { Bh = WvTh; Bl = WvTl; Ch = vh; Cl = vl; N = 4096;
                        ntile = nb - 16; mode = 1; }
    else              { Bh = WgTh; Bl = WgTl; C = dg; N = 4096;
                        ntile = nb - 32; mode = 0; }
    size_t aRow = (size_t)blockIdx.y * 128;
    size_t bRow = (size_t)ntile * 256;
    g256_core(Xh + aRow * HID, Xl + aRow * HID, Bh + bRow * HID, Bl + bRow * HID,
              HID, N, aRow, bRow, mode, head, C, Ch, Cl, smem);
}

// generic single GEMM (Wo)
__global__ __launch_bounds__(G2_THREADS, 1) void gemm_n256(
    const __nv_bfloat16* __restrict__ Ah, const __nv_bfloat16* __restrict__ Al,
    const __nv_bfloat16* __restrict__ Bh, const __nv_bfloat16* __restrict__ Bl,
    float* __restrict__ C, int N, int K) {
    extern __shared__ char smem[];
    size_t aRow = (size_t)blockIdx.y * 128;
    size_t bRow = (size_t)blockIdx.x * 256;
    g256_core(Ah + aRow * K, Al + aRow * K, Bh + bRow * K, Bl + bRow * K,
              K, N, aRow, bRow, 0, 0, C, nullptr, nullptr, smem);
}

// ------------- prep: 5 weight transposes + X split, one launch -------------
// store phase packs 4 consecutive-k bf16 per thread (uint2 stores)
__global__ __launch_bounds__(256) void prep_all(
    const float* __restrict__ X,
    const float* __restrict__ Wq, const float* __restrict__ Wk,
    const float* __restrict__ Wv, const float* __restrict__ Wg,
    const float* __restrict__ Wo,
    __nv_bfloat16* __restrict__ Xh, __nv_bfloat16* __restrict__ Xl,
    __nv_bfloat16* __restrict__ WqTh, __nv_bfloat16* __restrict__ WqTl,
    __nv_bfloat16* __restrict__ WkTh, __nv_bfloat16* __restrict__ WkTl,
    __nv_bfloat16* __restrict__ WvTh, __nv_bfloat16* __restrict__ WvTl,
    __nv_bfloat16* __restrict__ WgTh, __nv_bfloat16* __restrict__ WgTl,
    __nv_bfloat16* __restrict__ WoTh, __nv_bfloat16* __restrict__ WoTl) {
    int id = blockIdx.x;
    if (id >= 32768) {
        int i = ((id - 32768) * 256 + threadIdx.x) * 4;
        float4 v = *(const float4*)(X + i);
        *(uint2*)(Xh + i) = make_uint2(pack_hi(v.x, v.y), pack_hi(v.z, v.w));
        *(uint2*)(Xl + i) = make_uint2(pack_lo(v.x, v.y), pack_lo(v.z, v.w));
        return;
    }
    __shared__ float ts[32][33];
    const float* in;
    __nv_bfloat16 *hT, *lT;
    int K, N, local;
    if (id < 4096)       { in = Wq; hT = WqTh; lT = WqTl; K = 2048; N = 2048; local = id; }
    else if (id < 8192)  { in = Wk; hT = WkTh; lT = WkTl; K = 2048; N = 2048; local = id - 4096; }
    else if (id < 16384) { in = Wv; hT = WvTh; lT = WvTl; K = 2048; N = 4096; local = id - 8192; }
    else if (id < 24576) { in = Wg; hT = WgTh; lT = WgTl; K = 2048; N = 4096; local = id - 16384; }
    else                 { in = Wo; hT = WoTh; lT = WoTl; K = 4096; N = 2048; local = id - 24576; }
    int nt = local % (N >> 5), kt = local / (N >> 5);
    int n0 = nt * 32, k0 = kt * 32;
    int tx = threadIdx.x & 31, ty = threadIdx.x >> 5;
#pragma unroll
    for (int r = 0; r < 4; r++)
        ts[ty + r * 8][tx] = in[(size_t)(k0 + ty + r * 8) * N + n0 + tx];
    __syncthreads();
    // store: thread -> (n = nn, k = kq*4..kq*4+3), packed uint2 writes
    {
        int nn = threadIdx.x >> 3;          // 0..31
        int kq = (threadIdx.x & 7) * 4;     // 0,4,..28
        int n = n0 + nn;
        float x0 = ts[kq + 0][nn];
        float x1 = ts[kq + 1][nn];
        float x2 = ts[kq + 2][nn];
        float x3 = ts[kq + 3][nn];
        size_t g = (size_t)n * K + k0 + kq;
        *(uint2*)(hT + g) = make_uint2(pack_hi(x0, x1), pack_hi(x2, x3));
        *(uint2*)(lT + g) = make_uint2(pack_lo(x0, x1), pack_lo(x2, x3));
    }
}

// ============ Tensor-core retention: i64 x j64, fused RMS+gate epilogue ============
#define RQh  0
#define RQl  32768
#define RKh  65536
#define RKl  98304
#define RV0h 131072
#define RV0l 147456
#define RV1h 163840
#define RV1l 180224
#define RSh  196608
#define RSl  204800
#define RET_TC_SMEM 212992

__device__ __forceinline__ void ret_issue_K64(uint32_t sb, int tid,
                                              const __nv_bfloat16* Kh,
                                              const __nv_bfloat16* Kl, size_t kb) {
#pragma unroll
    for (int u = 0; u < 4; u++) {
        int idx = tid + u * 512;
        int r = idx >> 5, c16 = (idx & 31) * 16;
        uint32_t so = r * 512 + ROWSWZ(r, c16);
        size_t ga = kb + (size_t)r * NQK + (c16 >> 1);
        CP_ASYNC16(sb + RKh + so, Kh + ga);
        CP_ASYNC16(sb + RKl + so, Kl + ga);
    }
}
__device__ __forceinline__ void ret_issue_V(uint32_t sb, int tid,
                                            const __nv_bfloat16* Vh,
                                            const __nv_bfloat16* Vl,
                                            size_t vbase, int grow,
                                            uint32_t bufh, uint32_t bufl) {
#pragma unroll
    for (int u = 0; u < 2; u++) {
        int idx = tid + u * 512;
        int r = idx >> 6, c16 = (idx & 63) * 16;
        uint32_t so = r * 1024 + ROWSWZ(r, c16);
        size_t ga = vbase + (size_t)(grow + r) * NVG + (c16 >> 1);
        CP_ASYNC16(sb + bufh + so, Vh + ga);
        CP_ASYNC16(sb + bufl + so, Vl + ga);
    }
}
__device__ __forceinline__ void ret_sv_phase(uint32_t sb, int lane, int wm, int wn,
                                             int p, uint32_t vbh, uint32_t vbl,
                                             float accO[16][4]) {
    const int ar = wm * 16 + (lane & 15);
    const int akb = (lane >> 4) * 16;
    uint32_t aoff = ar * 128 + ROWSWZ(ar, p * 32 + akb);
    uint32_t s0, s1, s2, s3, t0, t1, t2, t3;
    ldmx4(s0, s1, s2, s3, sb + RSh + aoff);
    ldmx4(t0, t1, t2, t3, sb + RSl + aoff);
    const int vr = lane & 15;
    const int vc = (lane >> 4) * 8;
#pragma unroll
    for (int nfp = 0; nfp < 8; nfp++) {
        uint32_t voff = vr * 1024 + ROWSWZ(vr, (wn * 128 + nfp * 16 + vc) * 2);
        uint32_t v0, v1, v2, v3, u0, u1, u2, u3;
        ldmx4t(v0, v1, v2, v3, sb + vbh + voff);
        mma16816(accO[2 * nfp][0], accO[2 * nfp][1], accO[2 * nfp][2],
                 accO[2 * nfp][3], s0, s1, s2, s3, v0, v1);
        mma16816(accO[2 * nfp + 1][0], accO[2 * nfp + 1][1], accO[2 * nfp + 1][2],
                 accO[2 * nfp + 1][3], s0, s1, s2, s3, v2, v3);
        ldmx4t(u0, u1, u2, u3, sb + vbl + voff);
        mma16816(accO[2 * nfp][0], accO[2 * nfp][1], accO[2 * nfp][2],
                 accO[2 * nfp][3], s0, s1, s2, s3, u0, u1);
        mma16816(accO[2 * nfp + 1][0], accO[2 * nfp + 1][1], accO[2 * nfp + 1][2],
                 accO[2 * nfp + 1][3], s0, s1, s2, s3, u2, u3);
        mma16816(accO[2 * nfp][0], accO[2 * nfp][1], accO[2 * nfp][2],
                 accO[2 * nfp][3], t0, t1, t2, t3, v0, v1);
        mma16816(accO[2 * nfp + 1][0], accO[2 * nfp + 1][1], accO[2 * nfp + 1][2],
                 accO[2 * nfp + 1][3], t0, t1, t2, t3, v2, v3);
    }
}

__global__ __launch_bounds__(512, 1) void retention_tc(
    const __nv_bfloat16* __restrict__ Qh, const __nv_bfloat16* __restrict__ Ql,
    const __nv_bfloat16* __restrict__ Kh, const __nv_bfloat16* __restrict__ Kl,
    const __nv_bfloat16* __restrict__ Vh, const __nv_bfloat16* __restrict__ Vl,
    const float* __restrict__ dg, const float* __restrict__ gw,
    __nv_bfloat16* __restrict__ Oh, __nv_bfloat16* __restrict__ Ol) {
    extern __shared__ char smem[];
    const uint32_t sb = smem_to_u32(smem);
    const int tid  = threadIdx.x;
    const int wid  = tid >> 5, lane = tid & 31;
    const int wm   = wid & 3;
    const int wn   = wid >> 2;

    const int it = 31 - blockIdx.x;
    const int h  = blockIdx.y;
    const int b  = blockIdx.z;
    const int i0 = it * 64;
    const float scale = 0.0625f;
    const float gamma = 1.0f - exp2f(-5.0f - (float)h);
    const float l2g   = log2f(gamma);

    const size_t kbase = (size_t)(b * TLEN) * NQK + h * DKh;
    const size_t vbase = (size_t)(b * TLEN) * NVG + h * DVh;

    int jt0 = 0;
    {
        float Dh = -24.0f / l2g;
        int jlow = i0 - 63 - (int)Dh;
        if (jlow > 0) jt0 = jlow >> 6;
    }
    const int jtmax = it;
    const int phmax = jtmax * 4 + 3;

    {
        const size_t qb = (size_t)(b * TLEN + i0) * NQK + h * DKh;
#pragma unroll
        for (int u = 0; u < 4; u++) {
            int idx = tid + u * 512;
            int r = idx >> 5, c16 = (idx & 31) * 16;
            uint32_t so = r * 512 + ROWSWZ(r, c16);
            size_t ga = qb + (size_t)r * NQK + (c16 >> 1);
            CP_ASYNC16(sb + RQh + so, Qh + ga);
            CP_ASYNC16(sb + RQl + so, Ql + ga);
        }
        ret_issue_K64(sb, tid, Kh, Kl, kbase + (size_t)(jt0 * 64) * NQK);
        CP_COMMIT();
        ret_issue_V(sb, tid, Vh, Vl, vbase, jt0 * 64,      RV0h, RV0l);
        CP_COMMIT();
        ret_issue_V(sb, tid, Vh, Vl, vbase, jt0 * 64 + 16, RV1h, RV1l);
        CP_COMMIT();
    }

    float accO[16][4];
#pragma unroll
    for (int nf = 0; nf < 16; nf++)
#pragma unroll
        for (int e = 0; e < 4; e++) accO[nf][e] = 0.f;

    for (int jt = jt0; jt <= jtmax; jt++) {
        const int j0 = jt * 64;
        const int jn = (jt + 1 <= jtmax) ? (jt + 1) : jtmax;
        const int phb = jt * 4 + 2;

        CP_WAIT(2);
        __syncthreads();

        float accS[2][4];
#pragma unroll
        for (int nf = 0; nf < 2; nf++)
#pragma unroll
            for (int e = 0; e < 4; e++) accS[nf][e] = 0.f;
        {
            const int ar = wm * 16 + (lane & 15);
            const int akb = (lane >> 4) * 16;
            const int kb_r = lane & 7;
            const int kb_kh = ((lane >> 3) & 1) * 8;
            const int kb_nf = ((lane >> 4) & 1) * 8;
#pragma unroll
            for (int ks = 0; ks < 16; ks++) {
                uint32_t aoff = ar * 512 + ROWSWZ(ar, ks * 32 + akb);
                uint32_t a0, a1, a2, a3, l0, l1, l2, l3;
                ldmx4(a0, a1, a2, a3, sb + RQh + aoff);
                ldmx4(l0, l1, l2, l3, sb + RQl + aoff);
                int brow = wn * 16 + kb_nf + kb_r;
                uint32_t boff = brow * 512 + ROWSWZ(brow, ks * 32 + kb_kh * 2);
                uint32_t kb0, kb1, kb2, kb3, kc0, kc1, kc2, kc3;
                ldmx4(kb0, kb1, kb2, kb3, sb + RKh + boff);
                mma16816(accS[0][0], accS[0][1], accS[0][2], accS[0][3],
                         a0, a1, a2, a3, kb0, kb1);
                mma16816(accS[1][0], accS[1][1], accS[1][2], accS[1][3],
                         a0, a1, a2, a3, kb2, kb3);
                ldmx4(kc0, kc1, kc2, kc3, sb + RKl + boff);
                mma16816(accS[0][0], accS[0][1], accS[0][2], accS[0][3],
                         a0, a1, a2, a3, kc0, kc1);
                mma16816(accS[1][0], accS[1][1], accS[1][2], accS[1][3],
                         a0, a1, a2, a3, kc2, kc3);
                mma16816(accS[0][0], accS[0][1], accS[0][2], accS[0][3],
                         l0, l1, l2, l3, kb0, kb1);
                mma16816(accS[1][0], accS[1][1], accS[1][2], accS[1][3],
                         l0, l1, l2, l3, kb2, kb3);
            }
        }
        {
            const int il = wm * 16 + (lane >> 2);
#pragma unroll
            for (int nf = 0; nf < 2; nf++) {
                int jl = wn * 16 + nf * 8 + (lane & 3) * 2;
#pragma unroll
                for (int half = 0; half < 2; half++) {
                    int r = il + half * 8;
                    int d0 = (i0 + r) - (j0 + jl);
                    int d1 = d0 - 1;
                    float w0 = (d0 >= 0) ? scale * exp2f(l2g * (float)d0) : 0.f;
                    float w1 = (d1 >= 0) ? scale * exp2f(l2g * (float)d1) : 0.f;
                    float s0 = accS[nf][half * 2 + 0] * w0;
                    float s1 = accS[nf][half * 2 + 1] * w1;
                    uint32_t so = r * 128 + ROWSWZ(r, jl * 2);
                    *(uint32_t*)(smem + RSh + so) = pack_hi(s0, s1);
                    *(uint32_t*)(smem + RSl + so) = pack_lo(s0, s1);
                }
            }
        }
        __syncthreads();
        ret_issue_K64(sb, tid, Kh, Kl, kbase + (size_t)(jn * 64) * NQK);
        CP_COMMIT();

#pragma unroll
        for (int p = 0; p < 4; p++) {
            if (p < 2) { CP_WAIT(2); } else { CP_WAIT(1); }
            __syncthreads();
            uint32_t bh_ = (p & 1) ? RV1h : RV0h;
            uint32_t bl_ = (p & 1) ? RV1l : RV0l;
            ret_sv_phase(sb, lane, wm, wn, p, bh_, bl_, accO);
            __syncthreads();
            int ph2 = phb + p;
            if (ph2 > phmax) ph2 = phmax;
            ret_issue_V(sb, tid, Vh, Vl, vbase, ph2 * 16, bh_, bl_);
            CP_COMMIT();
        }
    }
    CP_WAIT(0);
    __syncthreads();

    // ---- fused epilogue: RMS over DV=512 + SiLU gate + hi/lo split ----
    {
        float ss0 = 0.f, ss1 = 0.f;
#pragma unroll
        for (int nf = 0; nf < 16; nf++) {
            ss0 += accO[nf][0] * accO[nf][0] + accO[nf][1] * accO[nf][1];
            ss1 += accO[nf][2] * accO[nf][2] + accO[nf][3] * accO[nf][3];
        }
        ss0 += __shfl_xor_sync(0xFFFFFFFFu, ss0, 1);
        ss0 += __shfl_xor_sync(0xFFFFFFFFu, ss0, 2);
        ss1 += __shfl_xor_sync(0xFFFFFFFFu, ss1, 1);
        ss1 += __shfl_xor_sync(0xFFFFFFFFu, ss1, 2);

        float* rs = (float*)smem;
        const int r0 = wm * 16 + (lane >> 2);
        if ((lane & 3) == 0) {
            rs[r0 * 4 + wn]       = ss0;
            rs[(r0 + 8) * 4 + wn] = ss1;
        }
        __syncthreads();
        float tot0 = rs[r0 * 4 + 0] + rs[r0 * 4 + 1] + rs[r0 * 4 + 2] + rs[r0 * 4 + 3];
        float tot1 = rs[(r0 + 8) * 4 + 0] + rs[(r0 + 8) * 4 + 1]
                   + rs[(r0 + 8) * 4 + 2] + rs[(r0 + 8) * 4 + 3];
        float rms0 = rsqrtf(tot0 * (1.0f / 512.0f) + 1e-5f);
        float rms1 = rsqrtf(tot1 * (1.0f / 512.0f) + 1e-5f);

        size_t row0 = (size_t)(b * TLEN + i0 + r0);
        size_t row1 = row0 + 8;
#pragma unroll
        for (int nf = 0; nf < 16; nf++) {
            int cl = wn * 128 + nf * 8 + (lane & 3) * 2;
            size_t col = (size_t)h * DVh + cl;
            float w0 = gw[cl], w1 = gw[cl + 1];
            float g00 = dg[row0 * NVG + col], g01 = dg[row0 * NVG + col + 1];
            float g10 = dg[row1 * NVG + col], g11 = dg[row1 * NVG + col + 1];
            float o00 = accO[nf][0] * rms0 * w0 * (g00 / (1.f + expf(-g00)));
            float o01 = accO[nf][1] * rms0 * w1 * (g01 / (1.f + expf(-g01)));
            float o10 = accO[nf][2] * rms1 * w0 * (g10 / (1.f + expf(-g10)));
            float o11 = accO[nf][3] * rms1 * w1 * (g11 / (1.f + expf(-g11)));
            *(uint32_t*)(Oh + row0 * NVG + col) = pack_hi(o00, o01);
            *(uint32_t*)(Ol + row0 * NVG + col) = pack_lo(o00, o01);
            *(uint32_t*)(Oh + row1 * NVG + col) = pack_hi(o10, o11);
            *(uint32_t*)(Ol + row1 * NVG + col) = pack_lo(o10, o11);
        }
    }
}

extern "C" void kernel_launch(void* const* d_in, const int* in_sizes, int n_in,
                              void* d_out, int out_size) {
    const float* X   = (const float*)d_in[0];
    const float* Wq  = (const float*)d_in[1];
    const float* Wk  = (const float*)d_in[2];
    const float* Wv  = (const float*)d_in[3];
    const float* Wg  = (const float*)d_in[4];
    const float* Wo  = (const float*)d_in[5];
    const float* gnw = (const float*)d_in[6];
    float* out = (float*)d_out;

    unsigned char* pool = nullptr;
    cudaGetSymbolAddress((void**)&pool, g_pool);

    float* dq  = (float*)pool;
    float* dk  = dq  + 8388608;
    float* dv  = dk  + 8388608;
    float* dg  = dv  + 16777216;
    float* dro = dg  + 16777216;
    __nv_bfloat16* bf = (__nv_bfloat16*)(dro + 16777216);
    __nv_bfloat16* Xh   = bf;             __nv_bfloat16* Xl   = Xh   + 8388608;
    __nv_bfloat16* WqTh = Xl   + 8388608; __nv_bfloat16* WqTl = WqTh + 4194304;
    __nv_bfloat16* WkTh = WqTl + 4194304; __nv_bfloat16* WkTl = WkTh + 4194304;
    __nv_bfloat16* WvTh = WkTl + 4194304; __nv_bfloat16* WvTl = WvTh + 8388608;
    __nv_bfloat16* WgTh = WvTl + 8388608; __nv_bfloat16* WgTl = WgTh + 8388608;
    __nv_bfloat16* WoTh = WgTl + 8388608; __nv_bfloat16* WoTl = WoTh + 8388608;
    __nv_bfloat16* droH = WoTl + 8388608; __nv_bfloat16* droL = droH + 16777216;
    __nv_bfloat16* qh   = droL + 16777216; __nv_bfloat16* ql = qh + 8388608;
    __nv_bfloat16* kh   = ql + 8388608;    __nv_bfloat16* kl = kh + 8388608;
    __nv_bfloat16* vh   = kl + 8388608;    __nv_bfloat16* vl = vh + 16777216;

    cudaFuncSetAttribute(gemm_qkvg, cudaFuncAttributeMaxDynamicSharedMemorySize, G2_SMEM);
    cudaFuncSetAttribute(gemm_n256, cudaFuncAttributeMaxDynamicSharedMemorySize, G2_SMEM);
    cudaFuncSetAttribute(retention_tc, cudaFuncAttributeMaxDynamicSharedMemorySize,
                         RET_TC_SMEM);

    dim3 thr(256);
    prep_all<<<40960, thr>>>(X, Wq, Wk, Wv, Wg, Wo, Xh, Xl,
                             WqTh, WqTl, WkTh, WkTl, WvTh, WvTl,
                             WgTh, WgTl, WoTh, WoTl);

    gemm_qkvg<<<dim3(48, 32), dim3(G2_THREADS), G2_SMEM>>>(
        Xh, Xl, WqTh, WqTl, WkTh, WkTl, WvTh, WvTl, WgTh, WgTl,
        qh, ql, kh, kl, vh, vl, dg);

    retention_tc<<<dim3(32, HQ, 2), dim3(512), RET_TC_SMEM>>>(
        qh, ql, kh, kl, vh, vl, dg, gnw, droH, droL);

    gemm_n256<<<dim3(HID / 256, MTOT / 128), dim3(G2_THREADS), G2_SMEM>>>(
        droH, droL, WoTh, WoTl, out, HID, NVG);
}